// round 16
// baseline (speedup 1.0000x reference)
#include <cuda_runtime.h>
#include <cuda_bf16.h>
#include <cstdint>
#include <cstddef>

// ---------------- problem constants ----------------
#define BB 16
#define N0 4096

// scratch (device globals; allocation-free per harness rules)
__device__ float  g_bufB[16777216];           // 64 MB
__device__ float  g_newxyz[BB * 256 * 3];     // SA1 centroids
__device__ float  g_newxyz2[BB * 128 * 3];    // SA2 centroids
__device__ int    g_gi[131072];               // SA1 group indices
__device__ int    g_gi2[131072];              // SA2 group indices
__device__ __nv_bfloat16 g_l1hi[786432];      // l1 feats hi, (b*256+s)*192 + (c+3); pads stay 0
__device__ __nv_bfloat16 g_l1lo[786432];
__device__ __nv_bfloat16 g_l2hi[655360];      // l2 row*(320): [0..2]=xyz, [3..258]=feats, pads 0
__device__ __nv_bfloat16 g_l2lo[655360];
__device__ double g_sum[512];
__device__ double g_sumsq[512];
__device__ double g_m6[32];                   // layer-1 input moments: S[6], M-upper[21]
__device__ float  g_scale[512];
__device__ float  g_shift[512];
__device__ __nv_bfloat16 g_whi[278528];       // all 5 layers, pre-split transposed
__device__ __nv_bfloat16 g_wlo[278528];
__device__ float  g_pmax[1048576];            // pooled-raw max per 32-row block
__device__ float  g_pmin[1048576];

#define WOFF_L1B 0        // 64->128,  KPAD 64
#define WOFF_L2A 8192     // 131->128, KPAD 192
#define WOFF_L2B 32768    // 128->256, KPAD 128
#define WOFF_L3A 65536    // 259->256, KPAD 320
#define WOFF_L3B 147456   // 256->512, KPAD 256

// ---------------- bf16 pack helpers ----------------
__device__ __forceinline__ uint32_t pack_bf16x2(float lo, float hi) {
    uint32_t r;
    asm("cvt.rn.bf16x2.f32 %0, %1, %2;" : "=r"(r) : "f"(hi), "f"(lo));
    return r;
}
__device__ __forceinline__ float bf_lo(uint32_t p) { return __uint_as_float(p << 16); }
__device__ __forceinline__ float bf_hi(uint32_t p) { return __uint_as_float(p & 0xffff0000u); }

// ---------------- FPS body: register dist + redux argmax, ONE barrier/iter ----------------
// (512thr/NPT=8 for SA1; 256thr/NPT=1 for SA2 — frozen config, R13 showed 1024thr regresses.)
template <int NPT>
__device__ void fps_dev(const float* __restrict__ xyz, int n, int npoint,
                        float* __restrict__ newxyz, float* __restrict__ outxyz,
                        float* sm, int b, int bt) {
    float* sx = sm;
    float* sy = sm + n;
    float* sz = sm + 2 * n;
    __shared__ uint32_t pval[2][16];
    __shared__ uint32_t pidx[2][16];

    int tid = threadIdx.x;
    int wid = tid >> 5, lane = tid & 31;
    int nwarps = bt >> 5;
    const float* base = xyz + (size_t)b * 3 * n;
    for (int i = tid; i < n; i += bt) {
        sx[i] = base[i];
        sy[i] = base[n + i];
        sz[i] = base[2 * n + i];
    }
    __syncthreads();

    float px[NPT], py[NPT], pz[NPT], pd[NPT];
#pragma unroll
    for (int j = 0; j < NPT; j++) {
        int i = tid + j * bt;
        px[j] = sx[i]; py[j] = sy[i]; pz[j] = sz[i];
        pd[j] = 1e10f;
    }

    int far = 0;
    for (int t = 0; t < npoint; t++) {
        float cx = sx[far], cy = sy[far], cz = sz[far];
        if (tid == 0) {
            float* nw = &newxyz[(b * npoint + t) * 3];
            nw[0] = cx; nw[1] = cy; nw[2] = cz;
            outxyz[(size_t)b * 3 * npoint + t] = cx;
            outxyz[(size_t)b * 3 * npoint + npoint + t] = cy;
            outxyz[(size_t)b * 3 * npoint + 2 * npoint + t] = cz;
        }
        uint32_t bv; int bi;
#pragma unroll
        for (int j = 0; j < NPT; j++) {
            float dx = __fsub_rn(px[j], cx);
            float dy = __fsub_rn(py[j], cy);
            float dz = __fsub_rn(pz[j], cz);
            float d = __fadd_rn(__fadd_rn(__fmul_rn(dx, dx), __fmul_rn(dy, dy)), __fmul_rn(dz, dz));
            float dd = fminf(pd[j], d);
            pd[j] = dd;
            uint32_t bits = __float_as_uint(dd);
            if (j == 0) { bv = bits; bi = tid; }
            else if (bits > bv) { bv = bits; bi = tid + j * bt; }
        }
        int p = t & 1;
        uint32_t mval = __reduce_max_sync(0xffffffffu, bv);
        uint32_t cand = (bv == mval) ? (uint32_t)bi : 0xffffffffu;
        uint32_t midx = __reduce_min_sync(0xffffffffu, cand);
        if (lane == 0) { pval[p][wid] = mval; pidx[p][wid] = midx; }
        __syncthreads();
        uint32_t v = (lane < nwarps) ? pval[p][lane] : 0u;
        uint32_t ii = (lane < nwarps) ? pidx[p][lane] : 0xffffffffu;
        uint32_t m = __reduce_max_sync(0xffffffffu, v);
        uint32_t c2 = (v == m) ? ii : 0xffffffffu;
        far = (int)__reduce_min_sync(0xffffffffu, c2);
    }
}

// ---------------- weight prep body: one element ----------------
__device__ __forceinline__ void prep_elem(int i, const float* w1, const float* w2,
                                          const float* w3, const float* w4, const float* w5) {
    if (i >= 278528) return;
    const float* W;
    int CIN, COUT, KPAD, j;
    if (i < 8192)        { W = w1; CIN = 64;  COUT = 128; KPAD = 64;  j = i; }
    else if (i < 32768)  { W = w2; CIN = 131; COUT = 128; KPAD = 192; j = i - 8192; }
    else if (i < 65536)  { W = w3; CIN = 128; COUT = 256; KPAD = 128; j = i - 32768; }
    else if (i < 147456) { W = w4; CIN = 259; COUT = 256; KPAD = 320; j = i - 65536; }
    else                 { W = w5; CIN = 256; COUT = 512; KPAD = 256; j = i - 147456; }
    int n = j / KPAD, k = j - n * KPAD;
    float v = (k < CIN) ? W[(size_t)k * COUT + n] : 0.f;
    __nv_bfloat16 h = __float2bfloat16_rn(v);
    g_whi[i] = h;
    g_wlo[i] = __float2bfloat16_rn(v - __bfloat162float(h));
}

// ---------------- merged launch 0: FPS1 || weight prep ----------------
// blocks [0,16): FPS1 per batch (512 thr); blocks [16,560): prep 512 elems each.
__global__ void m0_fps1_prep(const float* __restrict__ l0_xyz,
                             float* __restrict__ nxyz1, float* __restrict__ o_l1xyz,
                             const float* __restrict__ w1, const float* __restrict__ w2,
                             const float* __restrict__ w3, const float* __restrict__ w4,
                             const float* __restrict__ w5) {
    extern __shared__ float sm[];
    if (blockIdx.x < 16) {
        fps_dev<8>(l0_xyz, 4096, 256, nxyz1, o_l1xyz, sm, blockIdx.x, 512);
    } else {
        int i = (blockIdx.x - 16) * 512 + threadIdx.x;
        prep_elem(i, w1, w2, w3, w4, w5);
    }
}

// ---------------- ball query body: one warp per (b,s) ----------------
__device__ void bq_dev(const float* __restrict__ xyz, const float* __restrict__ newxyz,
                       int n, int S, int K, float r2, int* __restrict__ gi,
                       const float* __restrict__ sxyz,
                       __nv_bfloat16* __restrict__ shi, __nv_bfloat16* __restrict__ slo,
                       const float* __restrict__ pts, int blkid) {
    __shared__ float sm27[27];
    int tid = threadIdx.x;
    int gt = blkid * blockDim.x + tid;
    if (pts && tid < 27) sm27[tid] = 0.f;
    if (shi && gt < BB * 128 * 3) {
        int b = gt / 384, rr = gt % 384;
        int c = rr >> 7, kk = rr & 127;
        float v = sxyz[gt];
        __nv_bfloat16 h = __float2bfloat16_rn(v);
        size_t o = (size_t)(b * 128 + kk) * 320 + c;
        shi[o] = h;
        slo[o] = __float2bfloat16_rn(v - __bfloat162float(h));
    }
    int gw = gt >> 5;
    int lane = gt & 31;
    int b = gw / S, s = gw % S;
    const float* nw = &newxyz[(b * S + s) * 3];
    float nx = nw[0], ny = nw[1], nz = nw[2];
    float nsq = __fadd_rn(__fadd_rn(__fmul_rn(nx, nx), __fmul_rn(ny, ny)), __fmul_rn(nz, nz));
    const float* px = xyz + (size_t)b * 3 * n;
    int* g = gi + (size_t)(b * S + s) * K;
    int cnt = 0, first = -1;
    for (int base = 0; base < n && cnt < K; base += 32) {
        int i = base + lane;
        float x = px[i], y = px[n + i], z = px[2 * n + i];
        float psq = __fadd_rn(__fadd_rn(__fmul_rn(x, x), __fmul_rn(y, y)), __fmul_rn(z, z));
        float dot = __fadd_rn(__fadd_rn(__fmul_rn(nx, x), __fmul_rn(ny, y)), __fmul_rn(nz, z));
        float sqr = __fsub_rn(__fadd_rn(nsq, psq), __fmul_rn(2.0f, dot));
        bool ok = !(sqr > r2);
        unsigned m = __ballot_sync(0xffffffffu, ok);
        if (first < 0 && m) first = base + __ffs(m) - 1;
        int pos = cnt + __popc(m & ((1u << lane) - 1u));
        if (ok && pos < K) g[pos] = i;
        cnt += __popc(m);
    }
    if (cnt > K) cnt = K;
    for (int p = cnt + lane; p < K; p += 32) g[p] = first;

    // ---- fused layer-1 input moments (SA1 only, K == 32) ----
    if (pts) {
        __syncwarp();
        int idx = g[lane];
        const float* pp = pts + (size_t)b * 3 * n;
        float in[6];
        in[0] = __fsub_rn(px[idx], nx);
        in[1] = __fsub_rn(px[n + idx], ny);
        in[2] = __fsub_rn(px[2 * n + idx], nz);
        in[3] = pp[idx];
        in[4] = pp[n + idx];
        in[5] = pp[2 * n + idx];
        float acc[27];
        int c = 0;
#pragma unroll
        for (int k = 0; k < 6; k++) acc[c++] = in[k];
#pragma unroll
        for (int k = 0; k < 6; k++)
#pragma unroll
            for (int l = k; l < 6; l++) acc[c++] = in[k] * in[l];
        __syncthreads();
#pragma unroll
        for (int i = 0; i < 27; i++) {
            float v = acc[i];
#pragma unroll
            for (int o = 16; o; o >>= 1) v += __shfl_xor_sync(0xffffffffu, v, o);
            if (lane == 0) atomicAdd(&sm27[i], v);
        }
        __syncthreads();
        if (tid < 27) atomicAdd(&g_m6[tid], (double)sm27[tid]);
    }
}

// ---------------- layer-1 BN finalize body ----------------
__device__ void fin6_dev(const float* __restrict__ W, const float* __restrict__ bias,
                         const float* __restrict__ gamma, const float* __restrict__ beta) {
    __shared__ double S[6], M[6][6];
    int tid = threadIdx.x;
    if (tid < 6) S[tid] = g_m6[tid];
    if (tid == 0) {
        int c = 6;
        for (int k = 0; k < 6; k++)
            for (int l = k; l < 6; l++) { M[k][l] = g_m6[c]; M[l][k] = g_m6[c]; c++; }
    }
    __syncthreads();
    if (tid < 64) {
        double w[6];
#pragma unroll
        for (int k = 0; k < 6; k++) w[k] = (double)W[k * 64 + tid];
        double bc = (double)bias[tid];
        double sw = 0.0;
#pragma unroll
        for (int k = 0; k < 6; k++) sw += S[k] * w[k];
        const double N = 131072.0;
        double mean = (sw + N * bc) / N;
        double q = 0.0;
#pragma unroll
        for (int k = 0; k < 6; k++)
#pragma unroll
            for (int l = 0; l < 6; l++) q += M[k][l] * w[k] * w[l];
        double ex2 = (q + 2.0 * bc * sw + N * bc * bc) / N;
        double var = ex2 - mean * mean;
        float sc = gamma[tid] * rsqrtf((float)var + 1e-5f);
        g_scale[tid] = sc;
        g_shift[tid] = beta[tid] - (float)mean * sc;
    }
    __syncthreads();
    if (tid < 27) g_m6[tid] = 0.0;  // reset for next graph replay
}

// ---------------- merged launch 1: ballquery1(+stats) || FPS2 ----------------
__global__ void m1_bq1_fps2(const float* __restrict__ l0_xyz, const float* __restrict__ l0_pts,
                            const float* __restrict__ nxyz1, int* __restrict__ gi1,
                            const float* __restrict__ l1xyz, float* __restrict__ nxyz2,
                            float* __restrict__ o_l2xyz) {
    extern __shared__ float sm[];
    if (blockIdx.x < 512) {
        bq_dev(l0_xyz, nxyz1, 4096, 256, 32, 0.04f, gi1,
               nullptr, nullptr, nullptr, l0_pts, blockIdx.x);
    } else {
        fps_dev<1>(l1xyz, 256, 128, nxyz2, o_l2xyz, sm, blockIdx.x - 512, 256);
    }
}

// ---------------- merged launch 2: ballquery2(+l2 split) || bn_finalize6 ----------------
__global__ void m2_bq2_fin6(const float* __restrict__ l1xyz, const float* __restrict__ nxyz2,
                            int* __restrict__ gi2, const float* __restrict__ o_l2xyz,
                            __nv_bfloat16* __restrict__ l2hi, __nv_bfloat16* __restrict__ l2lo,
                            const float* __restrict__ W1, const float* __restrict__ b1,
                            const float* __restrict__ g1, const float* __restrict__ be1) {
    if (blockIdx.x < 256) {
        bq_dev(l1xyz, nxyz2, 256, 128, 64, 0.0625f, gi2,
               o_l2xyz, l2hi, l2lo, nullptr, blockIdx.x);
    } else {
        fin6_dev(W1, b1, g1, be1);
    }
}

// ---------------- mma.sync helper ----------------
__device__ __forceinline__ void mma16816(float* c, const uint32_t* a, uint32_t b0, uint32_t b1) {
    asm volatile(
        "mma.sync.aligned.m16n8k16.row.col.f32.bf16.bf16.f32 "
        "{%0,%1,%2,%3}, {%4,%5,%6,%7}, {%8,%9}, {%0,%1,%2,%3};"
        : "+f"(c[0]), "+f"(c[1]), "+f"(c[2]), "+f"(c[3])
        : "r"(a[0]), "r"(a[1]), "r"(a[2]), "r"(a[3]), "r"(b0), "r"(b1));
}

// ---------------- HMMA bf16 split GEMM ----------------
// Block: 128 rows x COLS cols (n0 = blockIdx.y*COLS), K chunk 64.
// 16 warps as 4(m) x 4(n): warp owns 32 rows x NT*8 cols, NT = COLS/32.
// GATHER: 0 = plain fp32 A; 1 = fused gather + 6->64 layer-1;
//         2 = SA2 gather; 3 = SA3 pre-split rows.
template <int CIN, int COUT, int COLS, int GATHER, bool IN_BN, bool POOL>
__global__ void __launch_bounds__(512)
hm_gemm(const float* __restrict__ A, const __nv_bfloat16* __restrict__ Whi,
        const __nv_bfloat16* __restrict__ Wlo, const float* __restrict__ bias,
        float* __restrict__ out, const int* __restrict__ gi,
        const float* __restrict__ gxyz, const float* __restrict__ gnew,
        const float* __restrict__ gpts, const float* __restrict__ gb1) {
    constexpr int KPAD = (CIN + 63) & ~63;
    constexpr int NCH = KPAD / 64;
    constexpr int LD = 72;
    constexpr int NT = COLS / 32;
    extern __shared__ __nv_bfloat16 sh[];
    __nv_bfloat16* Ahi = sh;
    __nv_bfloat16* Alo = Ahi + 128 * LD;
    __nv_bfloat16* Bhi = Alo + 128 * LD;
    __nv_bfloat16* Blo = Bhi + COLS * LD;
    float* in6 = reinterpret_cast<float*>(Blo + COLS * LD);  // GATHER1: 128*8 floats
    float* W1s = in6 + 128 * 8;                              // 384
    float* b1s = W1s + 384;                                  // 64

    int tid = threadIdx.x;
    int lane = tid & 31, w = tid >> 5;
    int mw = w >> 2, nw = w & 3;
    int g = lane >> 2, tg = lane & 3;
    size_t row0 = (size_t)blockIdx.x * 128;
    int n0 = blockIdx.y * COLS;

    float acc[2][NT][4];
#pragma unroll
    for (int i = 0; i < 2; i++)
#pragma unroll
        for (int j = 0; j < NT; j++)
#pragma unroll
            for (int q = 0; q < 4; q++) acc[i][j][q] = 0.f;

    if (GATHER == 1) {
        for (int e = tid; e < 384; e += 512) W1s[e] = A[e];
        if (tid < 64) b1s[tid] = gb1[tid];
    }

    int kp = tid & 15;
    for (int ch = 0; ch < NCH; ch++) {
        int gk0 = ch * 64 + kp * 4;
        __syncthreads();
        float4 s4, t4;
        if (IN_BN || GATHER == 1) {
            s4 = *reinterpret_cast<const float4*>(&g_scale[gk0]);
            t4 = *reinterpret_cast<const float4*>(&g_shift[gk0]);
        }
        if (GATHER == 1) {
            for (int r = tid; r < 128; r += 512) {
                size_t R = row0 + r;
                int bb_ = (int)(R >> 13), s = (int)((R >> 5) & 255);
                int idx = gi[R];
                const float* px = gxyz + (size_t)bb_ * 3 * N0;
                const float* pp = gpts + (size_t)bb_ * 3 * N0;
                const float* nwp = gnew + (size_t)(bb_ * 256 + s) * 3;
                in6[r * 8 + 0] = __fsub_rn(px[idx], nwp[0]);
                in6[r * 8 + 1] = __fsub_rn(px[N0 + idx], nwp[1]);
                in6[r * 8 + 2] = __fsub_rn(px[2 * N0 + idx], nwp[2]);
                in6[r * 8 + 3] = pp[idx];
                in6[r * 8 + 4] = pp[N0 + idx];
                in6[r * 8 + 5] = pp[2 * N0 + idx];
            }
        }
        for (int e = tid; e < COLS * 16; e += 512) {
            int n = e >> 4;
            size_t gidx = (size_t)(n0 + n) * KPAD + gk0;
            *reinterpret_cast<uint2*>(&Bhi[n * LD + kp * 4]) =
                *reinterpret_cast<const uint2*>(Whi + gidx);
            *reinterpret_cast<uint2*>(&Blo[n * LD + kp * 4]) =
                *reinterpret_cast<const uint2*>(Wlo + gidx);
        }
        if (GATHER == 1) {
            __syncthreads();
            for (int e = tid; e < 128 * 16; e += 512) {
                int r = e >> 4;
                int c0 = kp * 4;
                float i0 = in6[r * 8 + 0], i1 = in6[r * 8 + 1], i2 = in6[r * 8 + 2];
                float i3 = in6[r * 8 + 3], i4 = in6[r * 8 + 4], i5 = in6[r * 8 + 5];
                float v[4];
#pragma unroll
                for (int q = 0; q < 4; q++) {
                    float a = b1s[c0 + q];
                    a += i0 * W1s[0 * 64 + c0 + q];
                    a += i1 * W1s[1 * 64 + c0 + q];
                    a += i2 * W1s[2 * 64 + c0 + q];
                    a += i3 * W1s[3 * 64 + c0 + q];
                    a += i4 * W1s[4 * 64 + c0 + q];
                    a += i5 * W1s[5 * 64 + c0 + q];
                    v[q] = a;
                }
                v[0] = fmaxf(v[0] * s4.x + t4.x, 0.f);
                v[1] = fmaxf(v[1] * s4.y + t4.y, 0.f);
                v[2] = fmaxf(v[2] * s4.z + t4.z, 0.f);
                v[3] = fmaxf(v[3] * s4.w + t4.w, 0.f);
                uint32_t h01 = pack_bf16x2(v[0], v[1]);
                uint32_t h23 = pack_bf16x2(v[2], v[3]);
                uint32_t l01 = pack_bf16x2(v[0] - bf_lo(h01), v[1] - bf_hi(h01));
                uint32_t l23 = pack_bf16x2(v[2] - bf_lo(h23), v[3] - bf_hi(h23));
                *reinterpret_cast<uint2*>(&Ahi[r * LD + kp * 4]) = make_uint2(h01, h23);
                *reinterpret_cast<uint2*>(&Alo[r * LD + kp * 4]) = make_uint2(l01, l23);
            }
        } else {
            for (int e = tid; e < 128 * 16; e += 512) {
                int r = e >> 4;
                if (GATHER == 2) {
                    size_t R = row0 + r;
                    int bb_ = (int)(R >> 13);
                    int idx = gi[R];
                    size_t rowoff = ((size_t)(bb_ * 256 + idx)) * 192;
                    if (gk0 >= 4) {
                        *reinterpret_cast<uint2*>(&Ahi[r * LD + kp * 4]) =
                            *reinterpret_cast<const uint2*>(g_l1hi + rowoff + gk0);
                        *reinterpret_cast<uint2*>(&Alo[r * LD + kp * 4]) =
                            *reinterpret_cast<const uint2*>(g_l1lo + rowoff + gk0);
                    } else {
                        size_t sidx = R >> 6;
#pragma unroll
                        for (int c = 0; c < 3; c++) {
                            float v = __fsub_rn(gxyz[(size_t)bb_ * 768 + c * 256 + idx],
                                                gnew[sidx * 3 + c]);
                            __nv_bfloat16 h = __float2bfloat16_rn(v);
                            Ahi[r * LD + c] = h;
                            Alo[r * LD + c] = __float2bfloat16_rn(v - __bfloat162float(h));
                        }
                        Ahi[r * LD + 3] = g_l1hi[rowoff + 3];
                        Alo[r * LD + 3] = g_l1lo[rowoff + 3];
                    }
                } else if (GATHER == 3) {
                    size_t rowoff = (row0 + r) * 320;
                    *reinterpret_cast<uint2*>(&Ahi[r * LD + kp * 4]) =
                        *reinterpret_cast<const uint2*>(g_l2hi + rowoff + gk0);
                    *reinterpret_cast<uint2*>(&Alo[r * LD + kp * 4]) =
                        *reinterpret_cast<const uint2*>(g_l2lo + rowoff + gk0);
                } else {
                    float4 v = *reinterpret_cast<const float4*>(&A[(row0 + r) * CIN + gk0]);
                    if (IN_BN) {
                        v.x = fmaxf(v.x * s4.x + t4.x, 0.f);
                        v.y = fmaxf(v.y * s4.y + t4.y, 0.f);
                        v.z = fmaxf(v.z * s4.z + t4.z, 0.f);
                        v.w = fmaxf(v.w * s4.w + t4.w, 0.f);
                    }
                    uint32_t h01 = pack_bf16x2(v.x, v.y);
                    uint32_t h23 = pack_bf16x2(v.z, v.w);
                    float r0 = v.x - bf_lo(h01), r1 = v.y - bf_hi(h01);
                    float r2 = v.z - bf_lo(h23), r3 = v.w - bf_hi(h23);
                    uint32_t l01 = pack_bf16x2(r0, r1);
                    uint32_t l23 = pack_bf16x2(r2, r3);
                    *reinterpret_cast<uint2*>(&Ahi[r * LD + kp * 4]) = make_uint2(h01, h23);
                    *reinterpret_cast<uint2*>(&Alo[r * LD + kp * 4]) = make_uint2(l01, l23);
                }
            }
        }
        __syncthreads();

#pragma unroll
        for (int ks = 0; ks < 4; ks++) {
            int k0 = ks * 16;
            uint32_t ah[2][4], al[2][4];
#pragma unroll
            for (int mt = 0; mt < 2; mt++) {
                int rm = mw * 32 + mt * 16;
                ah[mt][0] = *reinterpret_cast<uint32_t*>(&Ahi[(rm + g) * LD + k0 + tg * 2]);
                ah[mt][1] = *reinterpret_cast<uint32_t*>(&Ahi[(rm + g + 8) * LD + k0 + tg * 2]);
                ah[mt][2] = *reinterpret_cast<uint32_t*>(&Ahi[(rm + g) * LD + k0 + tg * 2 + 8]);
                ah[mt][3] = *reinterpret_cast<uint32_t*>(&Ahi[(rm + g + 8) * LD + k0 + tg * 2 + 8]);
                al[mt][0] = *reinterpret_cast<uint32_t*>(&Alo[(rm + g) * LD + k0 + tg * 2]);
                al[mt][1] = *reinterpret_cast<uint32_t*>(&Alo[(rm + g + 8) * LD + k0 + tg * 2]);
                al[mt][2] = *reinterpret_cast<uint32_t*>(&Alo[(rm + g) * LD + k0 + tg * 2 + 8]);
                al[mt][3] = *reinterpret_cast<uint32_t*>(&Alo[(rm + g + 8) * LD + k0 + tg * 2 + 8]);
            }
#pragma unroll
            for (int nt = 0; nt < NT; nt++) {
                int cn = nw * (NT * 8) + nt * 8 + g;
                uint32_t bh0 = *reinterpret_cast<uint32_t*>(&Bhi[cn * LD + k0 + tg * 2]);
                uint32_t bh1 = *reinterpret_cast<uint32_t*>(&Bhi[cn * LD + k0 + tg * 2 + 8]);
                uint32_t bl0 = *reinterpret_cast<uint32_t*>(&Blo[cn * LD + k0 + tg * 2]);
                uint32_t bl1 = *reinterpret_cast<uint32_t*>(&Blo[cn * LD + k0 + tg * 2 + 8]);
#pragma unroll
                for (int mt = 0; mt < 2; mt++) {
                    mma16816(acc[mt][nt], ah[mt], bh0, bh1);
                    mma16816(acc[mt][nt], ah[mt], bl0, bl1);
                    mma16816(acc[mt][nt], al[mt], bh0, bh1);
                }
            }
        }
    }
    __syncthreads();

    // ---- epilogue: bias + (write | pool) + per-channel stats ----
    float* ss = reinterpret_cast<float*>(sh);
    float* sq = ss + COLS;
    for (int c = tid; c < COLS; c += 512) { ss[c] = 0.f; sq[c] = 0.f; }
    __syncthreads();

    int rb32 = (int)(row0 >> 5) + mw;
#pragma unroll
    for (int nt = 0; nt < NT; nt++) {
        int lc = nw * (NT * 8) + nt * 8 + tg * 2;
        float b0 = bias[n0 + lc], b1 = bias[n0 + lc + 1];
        float s0 = 0.f, q0 = 0.f, s1 = 0.f, q1 = 0.f;
        float mx0 = -3.4e38f, mn0 = 3.4e38f, mx1 = -3.4e38f, mn1 = 3.4e38f;
#pragma unroll
        for (int mt = 0; mt < 2; mt++) {
            float v00 = acc[mt][nt][0] + b0, v01 = acc[mt][nt][1] + b1;
            float v10 = acc[mt][nt][2] + b0, v11 = acc[mt][nt][3] + b1;
            if (!POOL) {
                size_t r0 = row0 + mw * 32 + mt * 16 + g;
                *reinterpret_cast<float2*>(&out[r0 * COUT + n0 + lc]) = make_float2(v00, v01);
                *reinterpret_cast<float2*>(&out[(r0 + 8) * COUT + n0 + lc]) = make_float2(v10, v11);
            }
            s0 += v00 + v10; q0 += v00 * v00 + v10 * v10;
            s1 += v01 + v11; q1 += v01 * v01 + v11 * v11;
            mx0 = fmaxf(mx0, fmaxf(v00, v10)); mn0 = fminf(mn0, fminf(v00, v10));
            mx1 = fmaxf(mx1, fmaxf(v01, v11)); mn1 = fminf(mn1, fminf(v01, v11));
        }
#pragma unroll
        for (int o = 4; o < 32; o <<= 1) {
            s0 += __shfl_xor_sync(0xffffffffu, s0, o);
            q0 += __shfl_xor_sync(0xffffffffu, q0, o);
            s1 += __shfl_xor_sync(0xffffffffu, s1, o);
            q1 += __shfl_xor_sync(0xffffffffu, q1, o);
            if (POOL) {
                mx0 = fmaxf(mx0, __shfl_xor_sync(0xffffffffu, mx0, o));
                mn0 = fminf(mn0, __shfl_xor_sync(0xffffffffu, mn0, o));
                mx1 = fmaxf(mx1, __shfl_xor_sync(0xffffffffu, mx1, o));
                mn1 = fminf(mn1, __shfl_xor_sync(0xffffffffu, mn1, o));
            }
        }
        if (g == 0) {
            atomicAdd(&ss[lc], s0);
            atomicAdd(&sq[lc], q0);
            atomicAdd(&ss[lc + 1], s1);
            atomicAdd(&sq[lc + 1], q1);
            if (POOL) {
                size_t pb = (size_t)rb32 * COUT + n0 + lc;
                g_pmax[pb] = mx0; g_pmin[pb] = mn0;
                g_pmax[pb + 1] = mx1; g_pmin[pb + 1] = mn1;
            }
        }
    }
    __syncthreads();
    for (int c = tid; c < COLS; c += 512) {
        atomicAdd(&g_sum[n0 + c], (double)ss[c]);
        atomicAdd(&g_sumsq[n0 + c], (double)sq[c]);
    }
}

// ---------------- pooled-raw -> BN + relu -> outputs ----------------
__global__ void pool_bn_out(int S, int KG, int C, float* __restrict__ out,
                            __nv_bfloat16* __restrict__ ohi, __nv_bfloat16* __restrict__ olo,
                            int ostride, float* __restrict__ zp, int zn) {
    if (zp && blockIdx.x == 0 && threadIdx.x < zn) zp[threadIdx.x] = 0.f;
    int total = BB * S * C;
    int stride = gridDim.x * blockDim.x;
    for (int i = blockIdx.x * blockDim.x + threadIdx.x; i < total; i += stride) {
        int c = i % C;
        int s = (i / C) % S;
        int b = i / (C * S);
        size_t base = ((size_t)(b * S + s) * KG) * C + c;
        float mx = g_pmax[base], mn = g_pmin[base];
        for (int q = 1; q < KG; q++) {
            mx = fmaxf(mx, g_pmax[base + (size_t)q * C]);
            mn = fminf(mn, g_pmin[base + (size_t)q * C]);
        }
        float sc = g_scale[c];
        float raw = (sc >= 0.f) ? mx : mn;
        float r = fmaxf(raw * sc + g_shift[c], 0.f);
        out[(size_t)b * C * S + (size_t)c * S + s] = r;
        if (ohi) {
            __nv_bfloat16 h = __float2bfloat16_rn(r);
            size_t o = (size_t)(b * S + s) * ostride + c + 3;
            ohi[o] = h;
            olo[o] = __float2bfloat16_rn(r - __bfloat162float(h));
        }
    }
}

// ---------------- BN finalize (also re-zeros accumulators for next use) ----------------
__global__ void bn_finalize_kernel(int C, double invcnt, const float* __restrict__ gamma,
                                   const float* __restrict__ beta) {
    int c = threadIdx.x;
    if (c < C) {
        double m = g_sum[c] * invcnt;
        double var = g_sumsq[c] * invcnt - m * m;
        float s = gamma[c] * rsqrtf((float)var + 1e-5f);
        g_scale[c] = s;
        g_shift[c] = beta[c] - (float)m * s;
    }
    g_sum[c] = 0.0;
    g_sumsq[c] = 0.0;
}

// ---------------- orchestration (single stream, 16 launches) ----------------
extern "C" void kernel_launch(void* const* d_in, const int* in_sizes, int n_in,
                              void* d_out, int out_size) {
    (void)in_sizes; (void)n_in; (void)out_size;
    const float* l0_xyz = (const float*)d_in[0];
    const float* l0_pts = (const float*)d_in[1];
    float* out = (float*)d_out;

    float* o_l1xyz = out;                 // 16*3*256   = 12288
    float* o_l1pts = out + 12288;         // 16*128*256 = 524288
    float* o_l2xyz = out + 536576;        // 16*3*128   = 6144
    float* o_l2pts = out + 542720;        // 16*256*128 = 524288
    float* o_l3xyz = out + 1067008;       // 16*3*1     = 48
    float* o_x     = out + 1067056;       // 16*512     = 8192

    float *bufB, *nxyz, *nxyz2;
    int *gi, *gi2;
    __nv_bfloat16 *whi, *wlo, *l1hi, *l1lo, *l2hi, *l2lo;
    cudaGetSymbolAddress((void**)&bufB, g_bufB);
    cudaGetSymbolAddress((void**)&nxyz, g_newxyz);
    cudaGetSymbolAddress((void**)&nxyz2, g_newxyz2);
    cudaGetSymbolAddress((void**)&gi, g_gi);
    cudaGetSymbolAddress((void**)&gi2, g_gi2);
    cudaGetSymbolAddress((void**)&whi, g_whi);
    cudaGetSymbolAddress((void**)&wlo, g_wlo);
    cudaGetSymbolAddress((void**)&l1hi, g_l1hi);
    cudaGetSymbolAddress((void**)&l1lo, g_l1lo);
    cudaGetSymbolAddress((void**)&l2hi, g_l2hi);
    cudaGetSymbolAddress((void**)&l2lo, g_l2lo);

    constexpr int FPS1_SM = 3 * 4096 * 4;
    constexpr int M1_SM = 3 * 256 * 4;
    cudaFuncSetAttribute((const void*)m0_fps1_prep, cudaFuncAttributeMaxDynamicSharedMemorySize, FPS1_SM);
    constexpr int HSM128 = (2 * 128 * 72 + 2 * 128 * 72) * 2;            // 73728
    constexpr int HSM256 = (2 * 128 * 72 + 2 * 256 * 72) * 2;            // 110592
    constexpr int HSM1G  = HSM128 + (128 * 8 + 384 + 64) * 4;            // 79616
    cudaFuncSetAttribute((const void*)hm_gemm<64, 128, 128, 1, true, true>,
                         cudaFuncAttributeMaxDynamicSharedMemorySize, HSM1G);
    cudaFuncSetAttribute((const void*)hm_gemm<131, 128, 128, 2, false, false>,
                         cudaFuncAttributeMaxDynamicSharedMemorySize, HSM128);
    cudaFuncSetAttribute((const void*)hm_gemm<128, 256, 256, 0, true, true>,
                         cudaFuncAttributeMaxDynamicSharedMemorySize, HSM256);
    cudaFuncSetAttribute((const void*)hm_gemm<259, 256, 128, 3, false, false>,
                         cudaFuncAttributeMaxDynamicSharedMemorySize, HSM128);
    cudaFuncSetAttribute((const void*)hm_gemm<256, 512, 128, 0, true, true>,
                         cudaFuncAttributeMaxDynamicSharedMemorySize, HSM128);

    // ================= M0: FPS1 || weight prep =================
    m0_fps1_prep<<<560, 512, FPS1_SM>>>(l0_xyz, nxyz, o_l1xyz,
                                        (const float*)d_in[6], (const float*)d_in[10],
                                        (const float*)d_in[14], (const float*)d_in[18],
                                        (const float*)d_in[22]);
    // M1: ballquery1(+layer-1 moments) || FPS2 (both depend only on FPS1)
    m1_bq1_fps2<<<528, 256, M1_SM>>>(l0_xyz, l0_pts, nxyz, gi, o_l1xyz, nxyz2, o_l2xyz);
    // M2: ballquery2(+l2 xyz split) || layer-1 BN finalize
    m2_bq2_fin6<<<257, 256>>>(o_l1xyz, nxyz2, gi2, o_l2xyz, l2hi, l2lo,
                              (const float*)d_in[2], (const float*)d_in[3],
                              (const float*)d_in[4], (const float*)d_in[5]);

    // SA1 MLP: fused gather + 6->64 + BN + 64->128 HMMA + pooled epilogue
    hm_gemm<64, 128, 128, 1, true, true><<<1024, 512, HSM1G>>>(
        (const float*)d_in[2], whi + WOFF_L1B, wlo + WOFF_L1B, (const float*)d_in[7],
        nullptr, gi, l0_xyz, nxyz, l0_pts, (const float*)d_in[3]);
    bn_finalize_kernel<<<1, 512>>>(128, 1.0 / 131072.0, (const float*)d_in[8], (const float*)d_in[9]);
    pool_bn_out<<<2048, 256>>>(256, 1, 128, o_l1pts, l1hi, l1lo, 192, nullptr, 0);

    // ================= SA2 MLP =================
    hm_gemm<131, 128, 128, 2, false, false><<<1024, 512, HSM128>>>(
        nullptr, whi + WOFF_L2A, wlo + WOFF_L2A, (const float*)d_in[11],
        bufB, gi2, o_l1xyz, nxyz2, nullptr, nullptr);
    bn_finalize_kernel<<<1, 512>>>(128, 1.0 / 131072.0, (const float*)d_in[12], (const float*)d_in[13]);

    hm_gemm<128, 256, 256, 0, true, true><<<1024, 512, HSM256>>>(
        bufB, whi + WOFF_L2B, wlo + WOFF_L2B, (const float*)d_in[15],
        nullptr, nullptr, nullptr, nullptr, nullptr, nullptr);
    bn_finalize_kernel<<<1, 512>>>(256, 1.0 / 131072.0, (const float*)d_in[16], (const float*)d_in[17]);
    pool_bn_out<<<2048, 256>>>(128, 2, 256, o_l2pts, l2hi, l2lo, 320, nullptr, 0);

    // ================= SA3 : group_all, rows = 2048 (column-split for occupancy) =================
    hm_gemm<259, 256, 128, 3, false, false><<<dim3(16, 2), 512, HSM128>>>(
        nullptr, whi + WOFF_L3A, wlo + WOFF_L3A, (const float*)d_in[19],
        bufB, nullptr, nullptr, nullptr, nullptr, nullptr);
    bn_finalize_kernel<<<1, 512>>>(256, 1.0 / 2048.0, (const float*)d_in[20], (const float*)d_in[21]);

    hm_gemm<256, 512, 128, 0, true, true><<<dim3(16, 4), 512, HSM128>>>(
        bufB, whi + WOFF_L3B, wlo + WOFF_L3B, (const float*)d_in[23],
        nullptr, nullptr, nullptr, nullptr, nullptr, nullptr);
    bn_finalize_kernel<<<1, 512>>>(512, 1.0 / 2048.0, (const float*)d_in[24], (const float*)d_in[25]);

    pool_bn_out<<<64, 256>>>(1, 4, 512, o_x, nullptr, nullptr, 0, o_l3xyz, 48);
}

// round 17
// speedup vs baseline: 1.0649x; 1.0649x over previous
#include <cuda_runtime.h>
#include <cuda_bf16.h>
#include <cstdint>
#include <cstddef>

// ---------------- problem constants ----------------
#define BB 16
#define N0 4096

// scratch (device globals; allocation-free per harness rules)
__device__ float  g_bufB[16777216];           // 64 MB
__device__ float  g_newxyz[BB * 256 * 3];     // SA1 centroids
__device__ float  g_newxyz2[BB * 128 * 3];    // SA2 centroids
__device__ int    g_gi[131072];               // SA1 group indices
__device__ int    g_gi2[131072];              // SA2 group indices
__device__ __nv_bfloat16 g_l1hi[786432];      // l1 feats hi, (b*256+s)*192 + (c+3); pads stay 0
__device__ __nv_bfloat16 g_l1lo[786432];
__device__ __nv_bfloat16 g_l2hi[655360];      // l2 row*(320): [0..2]=xyz, [3..258]=feats, pads 0
__device__ __nv_bfloat16 g_l2lo[655360];
__device__ double g_sum[512];
__device__ double g_sumsq[512];
__device__ double g_m6[32];                   // layer-1 input moments: S[6], M-upper[21]
__device__ float  g_scale[512];
__device__ float  g_shift[512];
__device__ __nv_bfloat16 g_whi[278528];       // all 5 layers, pre-split transposed
__device__ __nv_bfloat16 g_wlo[278528];
__device__ float  g_pmax[1048576];            // pooled-raw max per 32-row block
__device__ float  g_pmin[1048576];

#define WOFF_L1B 0        // 64->128,  KPAD 64
#define WOFF_L2A 8192     // 131->128, KPAD 192
#define WOFF_L2B 32768    // 128->256, KPAD 128
#define WOFF_L3A 65536    // 259->256, KPAD 320
#define WOFF_L3B 147456   // 256->512, KPAD 256

// ---------------- bf16 pack helpers ----------------
__device__ __forceinline__ uint32_t pack_bf16x2(float lo, float hi) {
    uint32_t r;
    asm("cvt.rn.bf16x2.f32 %0, %1, %2;" : "=r"(r) : "f"(hi), "f"(lo));
    return r;
}
__device__ __forceinline__ float bf_lo(uint32_t p) { return __uint_as_float(p << 16); }
__device__ __forceinline__ float bf_hi(uint32_t p) { return __uint_as_float(p & 0xffff0000u); }

// ---------------- FPS body: register dist + redux argmax, ONE barrier/iter ----------------
// (512thr/NPT=8 for SA1; 256thr/NPT=1 for SA2 — frozen config.)
template <int NPT>
__device__ void fps_dev(const float* __restrict__ xyz, int n, int npoint,
                        float* __restrict__ newxyz, float* __restrict__ outxyz,
                        float* sm, int b, int bt) {
    float* sx = sm;
    float* sy = sm + n;
    float* sz = sm + 2 * n;
    __shared__ uint32_t pval[2][16];
    __shared__ uint32_t pidx[2][16];

    int tid = threadIdx.x;
    int wid = tid >> 5, lane = tid & 31;
    int nwarps = bt >> 5;
    const float* base = xyz + (size_t)b * 3 * n;
    for (int i = tid; i < n; i += bt) {
        sx[i] = base[i];
        sy[i] = base[n + i];
        sz[i] = base[2 * n + i];
    }
    __syncthreads();

    float px[NPT], py[NPT], pz[NPT], pd[NPT];
#pragma unroll
    for (int j = 0; j < NPT; j++) {
        int i = tid + j * bt;
        px[j] = sx[i]; py[j] = sy[i]; pz[j] = sz[i];
        pd[j] = 1e10f;
    }

    int far = 0;
    for (int t = 0; t < npoint; t++) {
        float cx = sx[far], cy = sy[far], cz = sz[far];
        if (tid == 0) {
            float* nw = &newxyz[(b * npoint + t) * 3];
            nw[0] = cx; nw[1] = cy; nw[2] = cz;
            outxyz[(size_t)b * 3 * npoint + t] = cx;
            outxyz[(size_t)b * 3 * npoint + npoint + t] = cy;
            outxyz[(size_t)b * 3 * npoint + 2 * npoint + t] = cz;
        }
        uint32_t bv; int bi;
#pragma unroll
        for (int j = 0; j < NPT; j++) {
            float dx = __fsub_rn(px[j], cx);
            float dy = __fsub_rn(py[j], cy);
            float dz = __fsub_rn(pz[j], cz);
            float d = __fadd_rn(__fadd_rn(__fmul_rn(dx, dx), __fmul_rn(dy, dy)), __fmul_rn(dz, dz));
            float dd = fminf(pd[j], d);
            pd[j] = dd;
            uint32_t bits = __float_as_uint(dd);
            if (j == 0) { bv = bits; bi = tid; }
            else if (bits > bv) { bv = bits; bi = tid + j * bt; }
        }
        int p = t & 1;
        uint32_t mval = __reduce_max_sync(0xffffffffu, bv);
        uint32_t cand = (bv == mval) ? (uint32_t)bi : 0xffffffffu;
        uint32_t midx = __reduce_min_sync(0xffffffffu, cand);
        if (lane == 0) { pval[p][wid] = mval; pidx[p][wid] = midx; }
        __syncthreads();
        uint32_t v = (lane < nwarps) ? pval[p][lane] : 0u;
        uint32_t ii = (lane < nwarps) ? pidx[p][lane] : 0xffffffffu;
        uint32_t m = __reduce_max_sync(0xffffffffu, v);
        uint32_t c2 = (v == m) ? ii : 0xffffffffu;
        far = (int)__reduce_min_sync(0xffffffffu, c2);
    }
}

// ---------------- weight prep body: one element ----------------
__device__ __forceinline__ void prep_elem(int i, const float* w1, const float* w2,
                                          const float* w3, const float* w4, const float* w5) {
    if (i >= 278528) return;
    const float* W;
    int CIN, COUT, KPAD, j;
    if (i < 8192)        { W = w1; CIN = 64;  COUT = 128; KPAD = 64;  j = i; }
    else if (i < 32768)  { W = w2; CIN = 131; COUT = 128; KPAD = 192; j = i - 8192; }
    else if (i < 65536)  { W = w3; CIN = 128; COUT = 256; KPAD = 128; j = i - 32768; }
    else if (i < 147456) { W = w4; CIN = 259; COUT = 256; KPAD = 320; j = i - 65536; }
    else                 { W = w5; CIN = 256; COUT = 512; KPAD = 256; j = i - 147456; }
    int n = j / KPAD, k = j - n * KPAD;
    float v = (k < CIN) ? W[(size_t)k * COUT + n] : 0.f;
    __nv_bfloat16 h = __float2bfloat16_rn(v);
    g_whi[i] = h;
    g_wlo[i] = __float2bfloat16_rn(v - __bfloat162float(h));
}

// ---------------- merged launch 0: FPS1 || weight prep ----------------
__global__ void m0_fps1_prep(const float* __restrict__ l0_xyz,
                             float* __restrict__ nxyz1, float* __restrict__ o_l1xyz,
                             const float* __restrict__ w1, const float* __restrict__ w2,
                             const float* __restrict__ w3, const float* __restrict__ w4,
                             const float* __restrict__ w5) {
    extern __shared__ float sm[];
    if (blockIdx.x < 16) {
        fps_dev<8>(l0_xyz, 4096, 256, nxyz1, o_l1xyz, sm, blockIdx.x, 512);
    } else {
        int i = (blockIdx.x - 16) * 512 + threadIdx.x;
        prep_elem(i, w1, w2, w3, w4, w5);
    }
}

// ---------------- ball query body: one warp per (b,s) ----------------
__device__ void bq_dev(const float* __restrict__ xyz, const float* __restrict__ newxyz,
                       int n, int S, int K, float r2, int* __restrict__ gi,
                       const float* __restrict__ sxyz,
                       __nv_bfloat16* __restrict__ shi, __nv_bfloat16* __restrict__ slo,
                       const float* __restrict__ pts, int blkid) {
    __shared__ float sm27[27];
    int tid = threadIdx.x;
    int gt = blkid * blockDim.x + tid;
    if (pts && tid < 27) sm27[tid] = 0.f;
    if (shi && gt < BB * 128 * 3) {
        int b = gt / 384, rr = gt % 384;
        int c = rr >> 7, kk = rr & 127;
        float v = sxyz[gt];
        __nv_bfloat16 h = __float2bfloat16_rn(v);
        size_t o = (size_t)(b * 128 + kk) * 320 + c;
        shi[o] = h;
        slo[o] = __float2bfloat16_rn(v - __bfloat162float(h));
    }
    int gw = gt >> 5;
    int lane = gt & 31;
    int b = gw / S, s = gw % S;
    const float* nw = &newxyz[(b * S + s) * 3];
    float nx = nw[0], ny = nw[1], nz = nw[2];
    float nsq = __fadd_rn(__fadd_rn(__fmul_rn(nx, nx), __fmul_rn(ny, ny)), __fmul_rn(nz, nz));
    const float* px = xyz + (size_t)b * 3 * n;
    int* g = gi + (size_t)(b * S + s) * K;
    int cnt = 0, first = -1;
    for (int base = 0; base < n && cnt < K; base += 32) {
        int i = base + lane;
        float x = px[i], y = px[n + i], z = px[2 * n + i];
        float psq = __fadd_rn(__fadd_rn(__fmul_rn(x, x), __fmul_rn(y, y)), __fmul_rn(z, z));
        float dot = __fadd_rn(__fadd_rn(__fmul_rn(nx, x), __fmul_rn(ny, y)), __fmul_rn(nz, z));
        float sqr = __fsub_rn(__fadd_rn(nsq, psq), __fmul_rn(2.0f, dot));
        bool ok = !(sqr > r2);
        unsigned m = __ballot_sync(0xffffffffu, ok);
        if (first < 0 && m) first = base + __ffs(m) - 1;
        int pos = cnt + __popc(m & ((1u << lane) - 1u));
        if (ok && pos < K) g[pos] = i;
        cnt += __popc(m);
    }
    if (cnt > K) cnt = K;
    for (int p = cnt + lane; p < K; p += 32) g[p] = first;

    // ---- fused layer-1 input moments (SA1 only, K == 32) ----
    if (pts) {
        __syncwarp();
        int idx = g[lane];
        const float* pp = pts + (size_t)b * 3 * n;
        float in[6];
        in[0] = __fsub_rn(px[idx], nx);
        in[1] = __fsub_rn(px[n + idx], ny);
        in[2] = __fsub_rn(px[2 * n + idx], nz);
        in[3] = pp[idx];
        in[4] = pp[n + idx];
        in[5] = pp[2 * n + idx];
        float acc[27];
        int c = 0;
#pragma unroll
        for (int k = 0; k < 6; k++) acc[c++] = in[k];
#pragma unroll
        for (int k = 0; k < 6; k++)
#pragma unroll
            for (int l = k; l < 6; l++) acc[c++] = in[k] * in[l];
        __syncthreads();
#pragma unroll
        for (int i = 0; i < 27; i++) {
            float v = acc[i];
#pragma unroll
            for (int o = 16; o; o >>= 1) v += __shfl_xor_sync(0xffffffffu, v, o);
            if (lane == 0) atomicAdd(&sm27[i], v);
        }
        __syncthreads();
        if (tid < 27) atomicAdd(&g_m6[tid], (double)sm27[tid]);
    }
}

// ---------------- layer-1 BN finalize body ----------------
__device__ void fin6_dev(const float* __restrict__ W, const float* __restrict__ bias,
                         const float* __restrict__ gamma, const float* __restrict__ beta) {
    __shared__ double S[6], M[6][6];
    int tid = threadIdx.x;
    if (tid < 6) S[tid] = g_m6[tid];
    if (tid == 0) {
        int c = 6;
        for (int k = 0; k < 6; k++)
            for (int l = k; l < 6; l++) { M[k][l] = g_m6[c]; M[l][k] = g_m6[c]; c++; }
    }
    __syncthreads();
    if (tid < 64) {
        double w[6];
#pragma unroll
        for (int k = 0; k < 6; k++) w[k] = (double)W[k * 64 + tid];
        double bc = (double)bias[tid];
        double sw = 0.0;
#pragma unroll
        for (int k = 0; k < 6; k++) sw += S[k] * w[k];
        const double N = 131072.0;
        double mean = (sw + N * bc) / N;
        double q = 0.0;
#pragma unroll
        for (int k = 0; k < 6; k++)
#pragma unroll
            for (int l = 0; l < 6; l++) q += M[k][l] * w[k] * w[l];
        double ex2 = (q + 2.0 * bc * sw + N * bc * bc) / N;
        double var = ex2 - mean * mean;
        float sc = gamma[tid] * rsqrtf((float)var + 1e-5f);
        g_scale[tid] = sc;
        g_shift[tid] = beta[tid] - (float)mean * sc;
    }
    __syncthreads();
    if (tid < 27) g_m6[tid] = 0.0;  // reset for next graph replay
}

// ---------------- merged launch 1: ballquery1(+stats) || FPS2 ----------------
__global__ void m1_bq1_fps2(const float* __restrict__ l0_xyz, const float* __restrict__ l0_pts,
                            const float* __restrict__ nxyz1, int* __restrict__ gi1,
                            const float* __restrict__ l1xyz, float* __restrict__ nxyz2,
                            float* __restrict__ o_l2xyz) {
    extern __shared__ float sm[];
    if (blockIdx.x < 512) {
        bq_dev(l0_xyz, nxyz1, 4096, 256, 32, 0.04f, gi1,
               nullptr, nullptr, nullptr, l0_pts, blockIdx.x);
    } else {
        fps_dev<1>(l1xyz, 256, 128, nxyz2, o_l2xyz, sm, blockIdx.x - 512, 256);
    }
}

// ---------------- merged launch 2: ballquery2(+l2 split) || bn_finalize6 ----------------
__global__ void m2_bq2_fin6(const float* __restrict__ l1xyz, const float* __restrict__ nxyz2,
                            int* __restrict__ gi2, const float* __restrict__ o_l2xyz,
                            __nv_bfloat16* __restrict__ l2hi, __nv_bfloat16* __restrict__ l2lo,
                            const float* __restrict__ W1, const float* __restrict__ b1,
                            const float* __restrict__ g1, const float* __restrict__ be1) {
    if (blockIdx.x < 256) {
        bq_dev(l1xyz, nxyz2, 256, 128, 64, 0.0625f, gi2,
               o_l2xyz, l2hi, l2lo, nullptr, blockIdx.x);
    } else {
        fin6_dev(W1, b1, g1, be1);
    }
}

// ---------------- mma.sync helper ----------------
__device__ __forceinline__ void mma16816(float* c, const uint32_t* a, uint32_t b0, uint32_t b1) {
    asm volatile(
        "mma.sync.aligned.m16n8k16.row.col.f32.bf16.bf16.f32 "
        "{%0,%1,%2,%3}, {%4,%5,%6,%7}, {%8,%9}, {%0,%1,%2,%3};"
        : "+f"(c[0]), "+f"(c[1]), "+f"(c[2]), "+f"(c[3])
        : "r"(a[0]), "r"(a[1]), "r"(a[2]), "r"(a[3]), "r"(b0), "r"(b1));
}

// ---------------- HMMA bf16 split GEMM ----------------
// Block: 128 rows x COLS cols (n0 = blockIdx.y*COLS), K chunk 64.
// 16 warps as 4(m) x 4(n): warp owns 32 rows x NT*8 cols, NT = COLS/32.
// GATHER: 0 = plain fp32 A; 1 = fused gather + 6->64 layer-1;
//         2 = SA2 gather; 3 = SA3 pre-split rows.
// MINB: min blocks/SM hint (2 for COLS=128 variants -> regs <= 64, 2 blocks/SM).
template <int CIN, int COUT, int COLS, int GATHER, bool IN_BN, bool POOL, int MINB>
__global__ void __launch_bounds__(512, MINB)
hm_gemm(const float* __restrict__ A, const __nv_bfloat16* __restrict__ Whi,
        const __nv_bfloat16* __restrict__ Wlo, const float* __restrict__ bias,
        float* __restrict__ out, const int* __restrict__ gi,
        const float* __restrict__ gxyz, const float* __restrict__ gnew,
        const float* __restrict__ gpts, const float* __restrict__ gb1) {
    constexpr int KPAD = (CIN + 63) & ~63;
    constexpr int NCH = KPAD / 64;
    constexpr int LD = 72;
    constexpr int NT = COLS / 32;
    extern __shared__ __nv_bfloat16 sh[];
    __nv_bfloat16* Ahi = sh;
    __nv_bfloat16* Alo = Ahi + 128 * LD;
    __nv_bfloat16* Bhi = Alo + 128 * LD;
    __nv_bfloat16* Blo = Bhi + COLS * LD;
    float* in6 = reinterpret_cast<float*>(Blo + COLS * LD);  // GATHER1: 128*8 floats
    float* W1s = in6 + 128 * 8;                              // 384
    float* b1s = W1s + 384;                                  // 64

    int tid = threadIdx.x;
    int lane = tid & 31, w = tid >> 5;
    int mw = w >> 2, nw = w & 3;
    int g = lane >> 2, tg = lane & 3;
    size_t row0 = (size_t)blockIdx.x * 128;
    int n0 = blockIdx.y * COLS;

    float acc[2][NT][4];
#pragma unroll
    for (int i = 0; i < 2; i++)
#pragma unroll
        for (int j = 0; j < NT; j++)
#pragma unroll
            for (int q = 0; q < 4; q++) acc[i][j][q] = 0.f;

    if (GATHER == 1) {
        for (int e = tid; e < 384; e += 512) W1s[e] = A[e];
        if (tid < 64) b1s[tid] = gb1[tid];
    }

    int kp = tid & 15;
    for (int ch = 0; ch < NCH; ch++) {
        int gk0 = ch * 64 + kp * 4;
        __syncthreads();
        float4 s4, t4;
        if (IN_BN || GATHER == 1) {
            s4 = *reinterpret_cast<const float4*>(&g_scale[gk0]);
            t4 = *reinterpret_cast<const float4*>(&g_shift[gk0]);
        }
        if (GATHER == 1) {
            for (int r = tid; r < 128; r += 512) {
                size_t R = row0 + r;
                int bb_ = (int)(R >> 13), s = (int)((R >> 5) & 255);
                int idx = gi[R];
                const float* px = gxyz + (size_t)bb_ * 3 * N0;
                const float* pp = gpts + (size_t)bb_ * 3 * N0;
                const float* nwp = gnew + (size_t)(bb_ * 256 + s) * 3;
                in6[r * 8 + 0] = __fsub_rn(px[idx], nwp[0]);
                in6[r * 8 + 1] = __fsub_rn(px[N0 + idx], nwp[1]);
                in6[r * 8 + 2] = __fsub_rn(px[2 * N0 + idx], nwp[2]);
                in6[r * 8 + 3] = pp[idx];
                in6[r * 8 + 4] = pp[N0 + idx];
                in6[r * 8 + 5] = pp[2 * N0 + idx];
            }
        }
        for (int e = tid; e < COLS * 16; e += 512) {
            int n = e >> 4;
            size_t gidx = (size_t)(n0 + n) * KPAD + gk0;
            *reinterpret_cast<uint2*>(&Bhi[n * LD + kp * 4]) =
                *reinterpret_cast<const uint2*>(Whi + gidx);
            *reinterpret_cast<uint2*>(&Blo[n * LD + kp * 4]) =
                *reinterpret_cast<const uint2*>(Wlo + gidx);
        }
        if (GATHER == 1) {
            __syncthreads();
            for (int e = tid; e < 128 * 16; e += 512) {
                int r = e >> 4;
                int c0 = kp * 4;
                float i0 = in6[r * 8 + 0], i1 = in6[r * 8 + 1], i2 = in6[r * 8 + 2];
                float i3 = in6[r * 8 + 3], i4 = in6[r * 8 + 4], i5 = in6[r * 8 + 5];
                float v[4];
#pragma unroll
                for (int q = 0; q < 4; q++) {
                    float a = b1s[c0 + q];
                    a += i0 * W1s[0 * 64 + c0 + q];
                    a += i1 * W1s[1 * 64 + c0 + q];
                    a += i2 * W1s[2 * 64 + c0 + q];
                    a += i3 * W1s[3 * 64 + c0 + q];
                    a += i4 * W1s[4 * 64 + c0 + q];
                    a += i5 * W1s[5 * 64 + c0 + q];
                    v[q] = a;
                }
                v[0] = fmaxf(v[0] * s4.x + t4.x, 0.f);
                v[1] = fmaxf(v[1] * s4.y + t4.y, 0.f);
                v[2] = fmaxf(v[2] * s4.z + t4.z, 0.f);
                v[3] = fmaxf(v[3] * s4.w + t4.w, 0.f);
                uint32_t h01 = pack_bf16x2(v[0], v[1]);
                uint32_t h23 = pack_bf16x2(v[2], v[3]);
                uint32_t l01 = pack_bf16x2(v[0] - bf_lo(h01), v[1] - bf_hi(h01));
                uint32_t l23 = pack_bf16x2(v[2] - bf_lo(h23), v[3] - bf_hi(h23));
                *reinterpret_cast<uint2*>(&Ahi[r * LD + kp * 4]) = make_uint2(h01, h23);
                *reinterpret_cast<uint2*>(&Alo[r * LD + kp * 4]) = make_uint2(l01, l23);
            }
        } else {
            for (int e = tid; e < 128 * 16; e += 512) {
                int r = e >> 4;
                if (GATHER == 2) {
                    size_t R = row0 + r;
                    int bb_ = (int)(R >> 13);
                    int idx = gi[R];
                    size_t rowoff = ((size_t)(bb_ * 256 + idx)) * 192;
                    if (gk0 >= 4) {
                        *reinterpret_cast<uint2*>(&Ahi[r * LD + kp * 4]) =
                            *reinterpret_cast<const uint2*>(g_l1hi + rowoff + gk0);
                        *reinterpret_cast<uint2*>(&Alo[r * LD + kp * 4]) =
                            *reinterpret_cast<const uint2*>(g_l1lo + rowoff + gk0);
                    } else {
                        size_t sidx = R >> 6;
#pragma unroll
                        for (int c = 0; c < 3; c++) {
                            float v = __fsub_rn(gxyz[(size_t)bb_ * 768 + c * 256 + idx],
                                                gnew[sidx * 3 + c]);
                            __nv_bfloat16 h = __float2bfloat16_rn(v);
                            Ahi[r * LD + c] = h;
                            Alo[r * LD + c] = __float2bfloat16_rn(v - __bfloat162float(h));
                        }
                        Ahi[r * LD + 3] = g_l1hi[rowoff + 3];
                        Alo[r * LD + 3] = g_l1lo[rowoff + 3];
                    }
                } else if (GATHER == 3) {
                    size_t rowoff = (row0 + r) * 320;
                    *reinterpret_cast<uint2*>(&Ahi[r * LD + kp * 4]) =
                        *reinterpret_cast<const uint2*>(g_l2hi + rowoff + gk0);
                    *reinterpret_cast<uint2*>(&Alo[r * LD + kp * 4]) =
                        *reinterpret_cast<const uint2*>(g_l2lo + rowoff + gk0);
                } else {
                    float4 v = *reinterpret_cast<const float4*>(&A[(row0 + r) * CIN + gk0]);
                    if (IN_BN) {
                        v.x = fmaxf(v.x * s4.x + t4.x, 0.f);
                        v.y = fmaxf(v.y * s4.y + t4.y, 0.f);
                        v.z = fmaxf(v.z * s4.z + t4.z, 0.f);
                        v.w = fmaxf(v.w * s4.w + t4.w, 0.f);
                    }
                    uint32_t h01 = pack_bf16x2(v.x, v.y);
                    uint32_t h23 = pack_bf16x2(v.z, v.w);
                    float r0 = v.x - bf_lo(h01), r1 = v.y - bf_hi(h01);
                    float r2 = v.z - bf_lo(h23), r3 = v.w - bf_hi(h23);
                    uint32_t l01 = pack_bf16x2(r0, r1);
                    uint32_t l23 = pack_bf16x2(r2, r3);
                    *reinterpret_cast<uint2*>(&Ahi[r * LD + kp * 4]) = make_uint2(h01, h23);
                    *reinterpret_cast<uint2*>(&Alo[r * LD + kp * 4]) = make_uint2(l01, l23);
                }
            }
        }
        __syncthreads();

#pragma unroll
        for (int ks = 0; ks < 4; ks++) {
            int k0 = ks * 16;
            uint32_t ah[2][4], al[2][4];
#pragma unroll
            for (int mt = 0; mt < 2; mt++) {
                int rm = mw * 32 + mt * 16;
                ah[mt][0] = *reinterpret_cast<uint32_t*>(&Ahi[(rm + g) * LD + k0 + tg * 2]);
                ah[mt][1] = *reinterpret_cast<uint32_t*>(&Ahi[(rm + g + 8) * LD + k0 + tg * 2]);
                ah[mt][2] = *reinterpret_cast<uint32_t*>(&Ahi[(rm + g) * LD + k0 + tg * 2 + 8]);
                ah[mt][3] = *reinterpret_cast<uint32_t*>(&Ahi[(rm + g + 8) * LD + k0 + tg * 2 + 8]);
                al[mt][0] = *reinterpret_cast<uint32_t*>(&Alo[(rm + g) * LD + k0 + tg * 2]);
                al[mt][1] = *reinterpret_cast<uint32_t*>(&Alo[(rm + g + 8) * LD + k0 + tg * 2]);
                al[mt][2] = *reinterpret_cast<uint32_t*>(&Alo[(rm + g) * LD + k0 + tg * 2 + 8]);
                al[mt][3] = *reinterpret_cast<uint32_t*>(&Alo[(rm + g + 8) * LD + k0 + tg * 2 + 8]);
            }
#pragma unroll
            for (int nt = 0; nt < NT; nt++) {
                int cn = nw * (NT * 8) + nt * 8 + g;
                uint32_t bh0 = *reinterpret_cast<uint32_t*>(&Bhi[cn * LD + k0 + tg * 2]);
                uint32_t bh1 = *reinterpret_cast<uint32_t*>(&Bhi[cn * LD + k0 + tg * 2 + 8]);
                uint32_t bl0 = *reinterpret_cast<uint32_t*>(&Blo[cn * LD + k0 + tg * 2]);
                uint32_t bl1 = *reinterpret_cast<uint32_t*>(&Blo[cn * LD + k0 + tg * 2 + 8]);
#pragma unroll
                for (int mt = 0; mt < 2; mt++) {
                    mma16816(acc[mt][nt], ah[mt], bh0, bh1);
                    mma16816(acc[mt][nt], ah[mt], bl0, bl1);
                    mma16816(acc[mt][nt], al[mt], bh0, bh1);
                }
            }
        }
    }
    __syncthreads();

    // ---- epilogue: bias + (write | pool) + per-channel stats ----
    float* ss = reinterpret_cast<float*>(sh);
    float* sq = ss + COLS;
    for (int c = tid; c < COLS; c += 512) { ss[c] = 0.f; sq[c] = 0.f; }
    __syncthreads();

    int rb32 = (int)(row0 >> 5) + mw;
#pragma unroll
    for (int nt = 0; nt < NT; nt++) {
        int lc = nw * (NT * 8) + nt * 8 + tg * 2;
        float b0 = bias[n0 + lc], b1 = bias[n0 + lc + 1];
        float s0 = 0.f, q0 = 0.f, s1 = 0.f, q1 = 0.f;
        float mx0 = -3.4e38f, mn0 = 3.4e38f, mx1 = -3.4e38f, mn1 = 3.4e38f;
#pragma unroll
        for (int mt = 0; mt < 2; mt++) {
            float v00 = acc[mt][nt][0] + b0, v01 = acc[mt][nt][1] + b1;
            float v10 = acc[mt][nt][2] + b0, v11 = acc[mt][nt][3] + b1;
            if (!POOL) {
                size_t r0 = row0 + mw * 32 + mt * 16 + g;
                *reinterpret_cast<float2*>(&out[r0 * COUT + n0 + lc]) = make_float2(v00, v01);
                *reinterpret_cast<float2*>(&out[(r0 + 8) * COUT + n0 + lc]) = make_float2(v10, v11);
            }
            s0 += v00 + v10; q0 += v00 * v00 + v10 * v10;
            s1 += v01 + v11; q1 += v01 * v01 + v11 * v11;
            mx0 = fmaxf(mx0, fmaxf(v00, v10)); mn0 = fminf(mn0, fminf(v00, v10));
            mx1 = fmaxf(mx1, fmaxf(v01, v11)); mn1 = fminf(mn1, fminf(v01, v11));
        }
#pragma unroll
        for (int o = 4; o < 32; o <<= 1) {
            s0 += __shfl_xor_sync(0xffffffffu, s0, o);
            q0 += __shfl_xor_sync(0xffffffffu, q0, o);
            s1 += __shfl_xor_sync(0xffffffffu, s1, o);
            q1 += __shfl_xor_sync(0xffffffffu, q1, o);
            if (POOL) {
                mx0 = fmaxf(mx0, __shfl_xor_sync(0xffffffffu, mx0, o));
                mn0 = fminf(mn0, __shfl_xor_sync(0xffffffffu, mn0, o));
                mx1 = fmaxf(mx1, __shfl_xor_sync(0xffffffffu, mx1, o));
                mn1 = fminf(mn1, __shfl_xor_sync(0xffffffffu, mn1, o));
            }
        }
        if (g == 0) {
            atomicAdd(&ss[lc], s0);
            atomicAdd(&sq[lc], q0);
            atomicAdd(&ss[lc + 1], s1);
            atomicAdd(&sq[lc + 1], q1);
            if (POOL) {
                size_t pb = (size_t)rb32 * COUT + n0 + lc;
                g_pmax[pb] = mx0; g_pmin[pb] = mn0;
                g_pmax[pb + 1] = mx1; g_pmin[pb + 1] = mn1;
            }
        }
    }
    __syncthreads();
    for (int c = tid; c < COLS; c += 512) {
        atomicAdd(&g_sum[n0 + c], (double)ss[c]);
        atomicAdd(&g_sumsq[n0 + c], (double)sq[c]);
    }
}

// ---------------- pooled-raw -> BN + relu -> outputs ----------------
__global__ void pool_bn_out(int S, int KG, int C, float* __restrict__ out,
                            __nv_bfloat16* __restrict__ ohi, __nv_bfloat16* __restrict__ olo,
                            int ostride, float* __restrict__ zp, int zn) {
    if (zp && blockIdx.x == 0 && threadIdx.x < zn) zp[threadIdx.x] = 0.f;
    int total = BB * S * C;
    int stride = gridDim.x * blockDim.x;
    for (int i = blockIdx.x * blockDim.x + threadIdx.x; i < total; i += stride) {
        int c = i % C;
        int s = (i / C) % S;
        int b = i / (C * S);
        size_t base = ((size_t)(b * S + s) * KG) * C + c;
        float mx = g_pmax[base], mn = g_pmin[base];
        for (int q = 1; q < KG; q++) {
            mx = fmaxf(mx, g_pmax[base + (size_t)q * C]);
            mn = fminf(mn, g_pmin[base + (size_t)q * C]);
        }
        float sc = g_scale[c];
        float raw = (sc >= 0.f) ? mx : mn;
        float r = fmaxf(raw * sc + g_shift[c], 0.f);
        out[(size_t)b * C * S + (size_t)c * S + s] = r;
        if (ohi) {
            __nv_bfloat16 h = __float2bfloat16_rn(r);
            size_t o = (size_t)(b * S + s) * ostride + c + 3;
            ohi[o] = h;
            olo[o] = __float2bfloat16_rn(r - __bfloat162float(h));
        }
    }
}

// ---------------- BN finalize (also re-zeros accumulators for next use) ----------------
__global__ void bn_finalize_kernel(int C, double invcnt, const float* __restrict__ gamma,
                                   const float* __restrict__ beta) {
    int c = threadIdx.x;
    if (c < C) {
        double m = g_sum[c] * invcnt;
        double var = g_sumsq[c] * invcnt - m * m;
        float s = gamma[c] * rsqrtf((float)var + 1e-5f);
        g_scale[c] = s;
        g_shift[c] = beta[c] - (float)m * s;
    }
    g_sum[c] = 0.0;
    g_sumsq[c] = 0.0;
}

// ---------------- orchestration (single stream, 16 launches) ----------------
extern "C" void kernel_launch(void* const* d_in, const int* in_sizes, int n_in,
                              void* d_out, int out_size) {
    (void)in_sizes; (void)n_in; (void)out_size;
    const float* l0_xyz = (const float*)d_in[0];
    const float* l0_pts = (const float*)d_in[1];
    float* out = (float*)d_out;

    float* o_l1xyz = out;                 // 16*3*256   = 12288
    float* o_l1pts = out + 12288;         // 16*128*256 = 524288
    float* o_l2xyz = out + 536576;        // 16*3*128   = 6144
    float* o_l2pts = out + 542720;        // 16*256*128 = 524288
    float* o_l3xyz = out + 1067008;       // 16*3*1     = 48
    float* o_x     = out + 1067056;       // 16*512     = 8192

    float *bufB, *nxyz, *nxyz2;
    int *gi, *gi2;
    __nv_bfloat16 *whi, *wlo, *l1hi, *l1lo, *l2hi, *l2lo;
    cudaGetSymbolAddress((void**)&bufB, g_bufB);
    cudaGetSymbolAddress((void**)&nxyz, g_newxyz);
    cudaGetSymbolAddress((void**)&nxyz2, g_newxyz2);
    cudaGetSymbolAddress((void**)&gi, g_gi);
    cudaGetSymbolAddress((void**)&gi2, g_gi2);
    cudaGetSymbolAddress((void**)&whi, g_whi);
    cudaGetSymbolAddress((void**)&wlo, g_wlo);
    cudaGetSymbolAddress((void**)&l1hi, g_l1hi);
    cudaGetSymbolAddress((void**)&l1lo, g_l1lo);
    cudaGetSymbolAddress((void**)&l2hi, g_l2hi);
    cudaGetSymbolAddress((void**)&l2lo, g_l2lo);

    constexpr int FPS1_SM = 3 * 4096 * 4;
    constexpr int M1_SM = 3 * 256 * 4;
    cudaFuncSetAttribute((const void*)m0_fps1_prep, cudaFuncAttributeMaxDynamicSharedMemorySize, FPS1_SM);
    constexpr int HSM128 = (2 * 128 * 72 + 2 * 128 * 72) * 2;            // 73728
    constexpr int HSM256 = (2 * 128 * 72 + 2 * 256 * 72) * 2;            // 110592
    constexpr int HSM1G  = HSM128 + (128 * 8 + 384 + 64) * 4;            // 79616
    cudaFuncSetAttribute((const void*)hm_gemm<64, 128, 128, 1, true, true, 2>,
                         cudaFuncAttributeMaxDynamicSharedMemorySize, HSM1G);
    cudaFuncSetAttribute((const void*)hm_gemm<131, 128, 128, 2, false, false, 2>,
                         cudaFuncAttributeMaxDynamicSharedMemorySize, HSM128);
    cudaFuncSetAttribute((const void*)hm_gemm<128, 256, 256, 0, true, true, 1>,
                         cudaFuncAttributeMaxDynamicSharedMemorySize, HSM256);
    cudaFuncSetAttribute((const void*)hm_gemm<259, 256, 128, 3, false, false, 2>,
                         cudaFuncAttributeMaxDynamicSharedMemorySize, HSM128);
    cudaFuncSetAttribute((const void*)hm_gemm<256, 512, 128, 0, true, true, 2>,
                         cudaFuncAttributeMaxDynamicSharedMemorySize, HSM128);

    // ================= M0: FPS1 || weight prep =================
    m0_fps1_prep<<<560, 512, FPS1_SM>>>(l0_xyz, nxyz, o_l1xyz,
                                        (const float*)d_in[6], (const float*)d_in[10],
                                        (const float*)d_in[14], (const float*)d_in[18],
                                        (const float*)d_in[22]);
    // M1: ballquery1(+layer-1 moments) || FPS2
    m1_bq1_fps2<<<528, 256, M1_SM>>>(l0_xyz, l0_pts, nxyz, gi, o_l1xyz, nxyz2, o_l2xyz);
    // M2: ballquery2(+l2 xyz split) || layer-1 BN finalize
    m2_bq2_fin6<<<257, 256>>>(o_l1xyz, nxyz2, gi2, o_l2xyz, l2hi, l2lo,
                              (const float*)d_in[2], (const float*)d_in[3],
                              (const float*)d_in[4], (const float*)d_in[5]);

    // SA1 MLP: fused gather + 6->64 + BN + 64->128 HMMA + pooled epilogue
    hm_gemm<64, 128, 128, 1, true, true, 2><<<1024, 512, HSM1G>>>(
        (const float*)d_in[2], whi + WOFF_L1B, wlo + WOFF_L1B, (const float*)d_in[7],
        nullptr, gi, l0_xyz, nxyz, l0_pts, (const float*)d_in[3]);
    bn_finalize_kernel<<<1, 512>>>(128, 1.0 / 131072.0, (const float*)d_in[8], (const float*)d_in[9]);
    pool_bn_out<<<2048, 256>>>(256, 1, 128, o_l1pts, l1hi, l1lo, 192, nullptr, 0);

    // ================= SA2 MLP =================
    hm_gemm<131, 128, 128, 2, false, false, 2><<<1024, 512, HSM128>>>(
        nullptr, whi + WOFF_L2A, wlo + WOFF_L2A, (const float*)d_in[11],
        bufB, gi2, o_l1xyz, nxyz2, nullptr, nullptr);
    bn_finalize_kernel<<<1, 512>>>(128, 1.0 / 131072.0, (const float*)d_in[12], (const float*)d_in[13]);

    hm_gemm<128, 256, 256, 0, true, true, 1><<<1024, 512, HSM256>>>(
        bufB, whi + WOFF_L2B, wlo + WOFF_L2B, (const float*)d_in[15],
        nullptr, nullptr, nullptr, nullptr, nullptr, nullptr);
    bn_finalize_kernel<<<1, 512>>>(256, 1.0 / 131072.0, (const float*)d_in[16], (const float*)d_in[17]);
    pool_bn_out<<<2048, 256>>>(128, 2, 256, o_l2pts, l2hi, l2lo, 320, nullptr, 0);

    // ================= SA3 : group_all, rows = 2048 (column-split) =================
    hm_gemm<259, 256, 128, 3, false, false, 2><<<dim3(16, 2), 512, HSM128>>>(
        nullptr, whi + WOFF_L3A, wlo + WOFF_L3A, (const float*)d_in[19],
        bufB, nullptr, nullptr, nullptr, nullptr, nullptr);
    bn_finalize_kernel<<<1, 512>>>(256, 1.0 / 2048.0, (const float*)d_in[20], (const float*)d_in[21]);

    hm_gemm<256, 512, 128, 0, true, true, 2><<<dim3(16, 4), 512, HSM128>>>(
        bufB, whi + WOFF_L3B, wlo + WOFF_L3B, (const float*)d_in[23],
        nullptr, nullptr, nullptr, nullptr, nullptr, nullptr);
    bn_finalize_kernel<<<1, 512>>>(512, 1.0 / 2048.0, (const float*)d_in[24], (const float*)d_in[25]);

    pool_bn_out<<<64, 256>>>(1, 4, 512, o_x, nullptr, nullptr, 0, o_l3xyz, 48);
}